// round 9
// baseline (speedup 1.0000x reference)
#include <cuda_runtime.h>
#include <cuda_bf16.h>
#include <math.h>

// ---------------------------------------------------------------------------
// mean over all (i,j) of: same(i,j) ? max(1-cos,0) : cos, with cos = pairwise
// cosine of row-normalized inputs.
//
// Algebraic collapse (clamp provably inactive; rel_err==0.0 confirmed):
//   sum = S1.S2 + sum_c [ cnt1_c*cnt2_c - 2 * T1_c . T2_c ]
// T_c = class-sum of normalized rows.  O(N*D).
//
// R8: R6->R7 showed time tracks LTS atomic-RMW op count (invisible to
// lts__throughput). This round has ZERO accumulation atomics:
//   K2: per-block dense partial tile [32 cls][64 quads] -> plain STG to
//       a private g_part slice. No fence, no election.
//   K3: one block per class sums the 256 partials from L2, writes g_T;
//       tiny 32-block election; last block finalizes + resets state.
// All scratch densely overwritten every replay -> no zeroing needed.
// ---------------------------------------------------------------------------

#define NCLASS   16
#define NCEFF    32           // 16 classes x 2 tensors
#define DIM      256
#define DIMQ     (DIM / 4)    // 64 dim-quads
#define ROWS_PB  32
#define MAXBLK   256          // (4096+4096)/32
#define NTHREADS 256

struct __align__(16) Entry {
    const float* ptr;
    float        inv;
    int          cls;
};

__device__ float4       g_part[MAXBLK][NCEFF][DIMQ];  // 8 MB, dense overwrite
__device__ int          g_cntp[MAXBLK][NCEFF];        // 32 KB, dense overwrite
__device__ float        g_T[NCEFF * DIM];             // 32 KB, K3 overwrites
__device__ int          g_cnt[NCEFF];
__device__ unsigned int g_done;

// ======================= K2: per-block partial tiles ========================
__global__ void __launch_bounds__(NTHREADS)
ci_partial_kernel(const float* __restrict__ x1,
                  const int* __restrict__ lab1, int n1,
                  const float* __restrict__ x2,
                  const int* __restrict__ lab2, int n2) {
    __shared__ Entry         sSorted[ROWS_PB];
    __shared__ const float*  sPtr[ROWS_PB];
    __shared__ int           sCls[ROWS_PB];
    __shared__ int           sPos[ROWS_PB];
    __shared__ int           sCnt[NCEFF];
    __shared__ int           sOff[NCEFF];

    const int tid  = threadIdx.x;
    const int lane = tid & 31;
    const int wid  = tid >> 5;
    const int bid  = blockIdx.x;

    if (tid < NCEFF) sCnt[tid] = 0;
    __syncthreads();

    const int ntot  = n1 + n2;
    const int base  = bid * ROWS_PB;
    const int chunk = min(ROWS_PB, ntot - base);   // >= 1 (grid sized exactly)

    // ---- prologue: labels, pointers, counts, ranks ------------------------
    if (tid < chunk) {
        int row = base + tid;
        const float* xp;
        int c;
        if (row < n1) { xp = x1 + (size_t)row * DIM;        c = lab1[row] & (NCLASS - 1); }
        else          { xp = x2 + (size_t)(row - n1) * DIM; c = (lab2[row - n1] & (NCLASS - 1)) + NCLASS; }
        sPtr[tid] = xp;
        sCls[tid] = c;
        sPos[tid] = atomicAdd(&sCnt[c], 1);
    }
    __syncthreads();

    // ---- warp 0: exclusive prefix scan of counts -> bucket offsets --------
    if (wid == 0) {
        int v = sCnt[lane];
        int s = v;
        #pragma unroll
        for (int o = 1; o < 32; o <<= 1) {
            int u = __shfl_up_sync(0xFFFFFFFFu, s, o);
            if (lane >= o) s += u;
        }
        sOff[lane] = s - v;   // exclusive
    }
    __syncthreads();

    // ---- norm pass: warp handles 4 rows, all loads front-batched ----------
    {
        const int i0 = wid * 4;
        const float4* ps[4];
        #pragma unroll
        for (int j = 0; j < 4; j++)
            ps[j] = reinterpret_cast<const float4*>(
                (i0 + j < chunk) ? sPtr[i0 + j] : x1);

        float4 A[4], B[4];
        #pragma unroll
        for (int j = 0; j < 4; j++) {
            A[j] = ps[j][lane * 2];
            B[j] = ps[j][lane * 2 + 1];
        }
        float ss[4];
        #pragma unroll
        for (int j = 0; j < 4; j++)
            ss[j] = A[j].x * A[j].x + A[j].y * A[j].y + A[j].z * A[j].z + A[j].w * A[j].w
                  + B[j].x * B[j].x + B[j].y * B[j].y + B[j].z * B[j].z + B[j].w * B[j].w;
        #pragma unroll
        for (int o = 16; o > 0; o >>= 1) {
            #pragma unroll
            for (int j = 0; j < 4; j++)
                ss[j] += __shfl_xor_sync(0xFFFFFFFFu, ss[j], o);
        }
        if (lane == 0) {
            #pragma unroll
            for (int j = 0; j < 4; j++) {
                int i = i0 + j;
                if (i < chunk) {
                    int c   = sCls[i];
                    int idx = sOff[c] + sPos[i];
                    sSorted[idx].ptr = (const float*)ps[j];
                    sSorted[idx].inv = 1.0f / fmaxf(sqrtf(ss[j]), 1e-8f);
                    sSorted[idx].cls = c;
                }
            }
        }
    }
    __syncthreads();

    // ---- phase B: two-pointer over sorted runs; dense STG partial tile ----
    // group gq (64 threads) owns classes [8gq, 8gq+8); thread owns quad q.
    {
        const int gq = tid >> 6;          // 0..3
        const int q  = tid & (DIMQ - 1);  // 0..63
        #pragma unroll
        for (int ci = 0; ci < 8; ci++) {
            int c = gq * 8 + ci;
            int s = sOff[c];
            int e = s + sCnt[c];
            float4 acc = make_float4(0.f, 0.f, 0.f, 0.f);
            for (int k = s; k < e; k++) {
                Entry en = sSorted[k];                              // bcast LDS.128
                float4 v = reinterpret_cast<const float4*>(en.ptr)[q];  // L1 hit
                acc.x += v.x * en.inv;
                acc.y += v.y * en.inv;
                acc.z += v.z * en.inv;
                acc.w += v.w * en.inv;
            }
            g_part[bid][c][q] = acc;   // plain STG.128, fire-and-forget
        }
    }
    if (tid < NCEFF) g_cntp[bid][tid] = sCnt[tid];
}

// ======================= K3: reduce partials + finalize =====================
__global__ void __launch_bounds__(NTHREADS)
ci_reduce_kernel(float* __restrict__ out, int nblk, int n1, int n2) {
    __shared__ unsigned int sIsLast;
    __shared__ int          sCntRed[NTHREADS / 32];
    __shared__ double       sRed[NTHREADS / 32];

    const int tid  = threadIdx.x;
    const int lane = tid & 31;
    const int wid  = tid >> 5;
    const int c    = blockIdx.x;   // one block per effective class
    const int d    = tid;          // dim

    // ---- sum this class's partials over all K2 blocks (L2 reads) ----------
    {
        float a0 = 0.f, a1 = 0.f, a2 = 0.f, a3 = 0.f;
        const float* pc = (const float*)&g_part[0][c][0];
        const size_t stride = (size_t)NCEFF * DIM;   // floats between blocks
        int b = 0;
        for (; b + 3 < nblk; b += 4) {
            a0 += pc[(size_t)(b + 0) * stride + d];
            a1 += pc[(size_t)(b + 1) * stride + d];
            a2 += pc[(size_t)(b + 2) * stride + d];
            a3 += pc[(size_t)(b + 3) * stride + d];
        }
        for (; b < nblk; b++)
            a0 += pc[(size_t)b * stride + d];
        g_T[c * DIM + d] = (a0 + a1) + (a2 + a3);
    }

    // ---- sum this class's counts -------------------------------------------
    {
        int v = (tid < nblk) ? g_cntp[tid][c] : 0;
        #pragma unroll
        for (int o = 16; o > 0; o >>= 1)
            v += __shfl_xor_sync(0xFFFFFFFFu, v, o);
        if (lane == 0) sCntRed[wid] = v;
        __syncthreads();
        if (tid == 0) {
            int t = 0;
            #pragma unroll
            for (int w = 0; w < NTHREADS / 32; w++) t += sCntRed[w];
            g_cnt[c] = t;
        }
    }

    // ---- tiny election over NCEFF blocks -----------------------------------
    __threadfence();
    __syncthreads();
    if (tid == 0)
        sIsLast = (atomicAdd(&g_done, 1u) == (unsigned)(NCEFF - 1));
    __syncthreads();
    if (!sIsLast) return;

    // ---- finalize ------------------------------------------------------------
    double s1 = 0.0, s2 = 0.0, t = 0.0;
    #pragma unroll
    for (int cc = 0; cc < NCLASS; cc++) {
        double av = (double)g_T[cc * DIM + d];
        double bv = (double)g_T[(cc + NCLASS) * DIM + d];
        s1 += av;
        s2 += bv;
        t  += av * bv;
    }
    double part = s1 * s2 - 2.0 * t;
    #pragma unroll
    for (int o = 16; o > 0; o >>= 1)
        part += __shfl_xor_sync(0xFFFFFFFFu, part, o);
    if (lane == 0) sRed[wid] = part;
    __syncthreads();
    if (tid == 0) {
        double tot = 0.0;
        #pragma unroll
        for (int w = 0; w < NTHREADS / 32; w++) tot += sRed[w];
        double cc = 0.0;
        #pragma unroll
        for (int k = 0; k < NCLASS; k++)
            cc += (double)g_cnt[k] * (double)g_cnt[k + NCLASS];
        out[0] = (float)((tot + cc) / ((double)n1 * (double)n2));
        g_done = 0u;   // only residual state; everything else densely overwritten
    }
}

extern "C" void kernel_launch(void* const* d_in, const int* in_sizes, int n_in,
                              void* d_out, int out_size) {
    const float* mmd1 = (const float*)d_in[0];
    const float* mmd2 = (const float*)d_in[1];
    const int*   lab1 = (const int*)d_in[2];
    const int*   lab2 = (const int*)d_in[3];

    int n1 = in_sizes[0] / DIM;
    int n2 = in_sizes[1] / DIM;
    int ntot = n1 + n2;
    int nblk = (ntot + ROWS_PB - 1) / ROWS_PB;
    if (nblk > MAXBLK) nblk = MAXBLK;   // fixed shapes: 256 exactly

    ci_partial_kernel<<<nblk, NTHREADS>>>(mmd1, lab1, n1, mmd2, lab2, n2);
    ci_reduce_kernel<<<NCEFF, NTHREADS>>>((float*)d_out, nblk, n1, n2);
}